// round 6
// baseline (speedup 1.0000x reference)
#include <cuda_runtime.h>

// ---------------- constants ----------------
#define H      256      // hidden
#define TXT    768
#define BIO    32
#define TM     64       // rows per CTA
#define NTHR   256
#define EPSLN  1e-5f

// ---------------- device scratch (precomputed folded weights) ----------------
__device__ float g_M [H * H];   // out_w @ Wv
__device__ float g_c [H];       // out_w @ bv + out_b
__device__ float g_Ag[H * H];   // (W1L @ M) * ln_text_g (column scaled)
__device__ float g_Bg[H * H];   // (W1R @ M) * ln_bio_g
__device__ float g_uA[H];       // (W1L@M) @ ln_text_g
__device__ float g_uB[H];       // (W1R@M) @ ln_bio_g
__device__ float g_e [H];       // (W1L@M)@ln_text_b + (W1R@M)@ln_bio_b + (W1L+W1R)@c + cls1_b

// ---------------- precompute 1: M = out_w @ Wv ; c = out_w @ bv + out_b ----------------
__global__ void precompute1(const float* __restrict__ in_proj_w,
                            const float* __restrict__ in_proj_b,
                            const float* __restrict__ out_w,
                            const float* __restrict__ out_b) {
    __shared__ float s_row[H];
    __shared__ float s_red[NTHR];
    int i = blockIdx.x, j = threadIdx.x;
    s_row[j] = out_w[i * H + j];
    __syncthreads();
    float acc = 0.f;
#pragma unroll 4
    for (int k = 0; k < H; k++)
        acc = fmaf(s_row[k], in_proj_w[(2 * H + k) * H + j], acc);
    g_M[i * H + j] = acc;

    // c[i] = sum_k out_w[i][k] * bv[k] + out_b[i]
    s_red[j] = s_row[j] * in_proj_b[2 * H + j];
    __syncthreads();
    for (int off = 128; off; off >>= 1) {
        if (j < off) s_red[j] += s_red[j + off];
        __syncthreads();
    }
    if (j == 0) g_c[i] = s_red[0] + out_b[i];
}

// ---------------- precompute 2: Ag, Bg, uA, uB, e ----------------
__global__ void precompute2(const float* __restrict__ cls1_w,
                            const float* __restrict__ cls1_b,
                            const float* __restrict__ ln_text_g,
                            const float* __restrict__ ln_text_b,
                            const float* __restrict__ ln_bio_g,
                            const float* __restrict__ ln_bio_b) {
    __shared__ float s_l[H], s_r[H];
    __shared__ float s_red[NTHR];
    int i = blockIdx.x, j = threadIdx.x;
    s_l[j] = cls1_w[i * 2 * H + j];         // W1L row i
    s_r[j] = cls1_w[i * 2 * H + H + j];     // W1R row i
    __syncthreads();

    float a = 0.f, b = 0.f;
#pragma unroll 4
    for (int k = 0; k < H; k++) {
        float m = g_M[k * H + j];
        a = fmaf(s_l[k], m, a);
        b = fmaf(s_r[k], m, b);
    }
    float gt = ln_text_g[j], gb = ln_bio_g[j];
    g_Ag[i * H + j] = a * gt;
    g_Bg[i * H + j] = b * gb;

    float eterm = a * ln_text_b[j] + b * ln_bio_b[j] + (s_l[j] + s_r[j]) * g_c[j];

    // three block reductions
    float vals[3] = {a * gt, b * gb, eterm};
    float res[3];
#pragma unroll
    for (int r = 0; r < 3; r++) {
        s_red[j] = vals[r];
        __syncthreads();
        for (int off = 128; off; off >>= 1) {
            if (j < off) s_red[j] += s_red[j + off];
            __syncthreads();
        }
        res[r] = s_red[0];
        __syncthreads();
    }
    if (j == 0) {
        g_uA[i] = res[0];
        g_uB[i] = res[1];
        g_e [i] = res[2] + cls1_b[i];
    }
}

// ---------------- main fused kernel ----------------
__device__ __forceinline__ void load8(float* d, const float* p) {
    float4 v0 = *(const float4*)p;
    float4 v1 = *(const float4*)(p + 4);
    d[0] = v0.x; d[1] = v0.y; d[2] = v0.z; d[3] = v0.w;
    d[4] = v1.x; d[5] = v1.y; d[6] = v1.z; d[7] = v1.w;
}

// smem floats: sX 32768 | s_w 8192 | s_a 2048 | vectors 2432  => 45440 floats
#define SMEM_FLOATS 45440
#define SMEM_BYTES  (SMEM_FLOATS * 4)

__global__ __launch_bounds__(NTHR, 1)
void fused_main(const float* __restrict__ bio,
                const float* __restrict__ text,
                const float* __restrict__ bio_w,
                const float* __restrict__ bio_b,
                const float* __restrict__ text_w,
                const float* __restrict__ text_b,
                const float* __restrict__ cls_ln_g,
                const float* __restrict__ cls_ln_b,
                const float* __restrict__ cls2_w,
                const float* __restrict__ cls2_b,
                float* __restrict__ out) {
    extern __shared__ float sm[];
    float* sX   = sm;                  // [64][512] : cols 0..255 = scaled x_t, 256..511 = scaled x_b
    float* s_w  = sX  + TM * 512;      // [32][256] staging (weights)
    float* s_a  = s_w + 32 * H;        // [32][64]  staging (activations, k-major)
    float* s_uA = s_a + 32 * TM;       // 256
    float* s_uB = s_uA + H;            // 256
    float* s_e  = s_uB + H;            // 256
    float* s_cg = s_e  + H;            // 256 cls_ln_g
    float* s_cb = s_cg + H;            // 256 cls_ln_b
    float* s_c2 = s_cb + H;            // 512 cls2_w
    float* s_tb = s_c2 + 2 * H;        // 256 text_b
    float* s_bb = s_tb + H;            // 256 bio_b
    float* s_at = s_bb + H;            // 64 alpha_text = -inv_t * m_t
    float* s_ab = s_at + TM;           // 64 alpha_bio

    const int tid = threadIdx.x;
    const int rg  = tid >> 5;          // warp id = row group (0..7)
    const int cg  = tid & 31;          // lane    = col group (0..31)
    const int R0  = rg * 8;
    const int C0  = cg * 8;
    const int row0 = blockIdx.x * TM;

    const float c2b0 = cls2_b[0];
    const float c2b1 = cls2_b[1];

    // ---- phase 0: stage small vectors + bio operands ----
    s_uA[tid] = g_uA[tid];
    s_uB[tid] = g_uB[tid];
    s_e [tid] = g_e [tid];
    s_cg[tid] = cls_ln_g[tid];
    s_cb[tid] = cls_ln_b[tid];
    s_c2[tid]       = cls2_w[tid];
    s_c2[H + tid]   = cls2_w[H + tid];
    s_tb[tid] = text_b[tid];
    s_bb[tid] = bio_b[tid];
    // bio_w [256][32] -> s_w[k][c]
    for (int idx = tid; idx < BIO * H; idx += NTHR) {
        int c = idx >> 5, k = idx & 31;
        s_w[k * H + c] = bio_w[idx];
    }
    // bio tile [64][32] -> s_a[k][r]
    for (int idx = tid; idx < TM * BIO; idx += NTHR) {
        int r = idx >> 5, k = idx & 31;
        s_a[k * TM + r] = bio[(row0 + r) * BIO + k];
    }
    __syncthreads();

    float acc[8][8];

    // ---- phase 1: bio GEMM  X_b[64][256] = bio @ bio_w^T + bio_b ----
#pragma unroll
    for (int i = 0; i < 8; i++)
#pragma unroll
        for (int j = 0; j < 8; j++) acc[i][j] = 0.f;

#pragma unroll 8
    for (int k = 0; k < BIO; k++) {
        float av[8], bv[8];
        load8(av, &s_a[k * TM + R0]);
        load8(bv, &s_w[k * H  + C0]);
#pragma unroll
        for (int i = 0; i < 8; i++)
#pragma unroll
            for (int j = 0; j < 8; j++)
                acc[i][j] = fmaf(av[i], bv[j], acc[i][j]);
    }
#pragma unroll
    for (int i = 0; i < 8; i++)
#pragma unroll
        for (int j = 0; j < 8; j++) acc[i][j] += s_bb[C0 + j];

    // LN stats per row (warp owns rows R0..R0+7), store scaled to sX cols 256..511
#pragma unroll
    for (int i = 0; i < 8; i++) {
        float s = 0.f, q = 0.f;
#pragma unroll
        for (int j = 0; j < 8; j++) { float v = acc[i][j]; s += v; q = fmaf(v, v, q); }
#pragma unroll
        for (int off = 16; off; off >>= 1) {
            s += __shfl_xor_sync(0xffffffffu, s, off);
            q += __shfl_xor_sync(0xffffffffu, q, off);
        }
        float m   = s * (1.f / H);
        float inv = rsqrtf(fmaf(q, 1.f / H, -m * m) + EPSLN);
        if (cg == 0) s_ab[R0 + i] = -inv * m;
        float4 v0 = make_float4(acc[i][0]*inv, acc[i][1]*inv, acc[i][2]*inv, acc[i][3]*inv);
        float4 v1 = make_float4(acc[i][4]*inv, acc[i][5]*inv, acc[i][6]*inv, acc[i][7]*inv);
        *(float4*)&sX[(R0 + i) * 512 + 256 + C0]     = v0;
        *(float4*)&sX[(R0 + i) * 512 + 256 + C0 + 4] = v1;
    }
    __syncthreads();

    // ---- phase 2: text GEMM  X_t[64][256] = text @ text_w^T + text_b ----
#pragma unroll
    for (int i = 0; i < 8; i++)
#pragma unroll
        for (int j = 0; j < 8; j++) acc[i][j] = 0.f;

    for (int kt = 0; kt < TXT / 32; kt++) {
        const int k0 = kt * 32;
        // stage text tile -> s_a[k][r]  (2048 floats, 512 float4)
#pragma unroll
        for (int u = 0; u < 2; u++) {
            int qd = tid + u * NTHR;           // 0..511
            int r  = qd >> 3;                  // 0..63
            int kq = qd & 7;                   // float4 index within 32 k
            float4 v = *(const float4*)&text[(row0 + r) * TXT + k0 + kq * 4];
            s_a[(kq * 4 + 0) * TM + r] = v.x;
            s_a[(kq * 4 + 1) * TM + r] = v.y;
            s_a[(kq * 4 + 2) * TM + r] = v.z;
            s_a[(kq * 4 + 3) * TM + r] = v.w;
        }
        // stage text_w tile -> s_w[k][c] (thread = output channel, 32B contiguous read)
        {
            const float4* src = (const float4*)&text_w[tid * TXT + k0];
#pragma unroll
            for (int u = 0; u < 8; u++) {
                float4 v = src[u];
                s_w[(u * 4 + 0) * H + tid] = v.x;
                s_w[(u * 4 + 1) * H + tid] = v.y;
                s_w[(u * 4 + 2) * H + tid] = v.z;
                s_w[(u * 4 + 3) * H + tid] = v.w;
            }
        }
        __syncthreads();
#pragma unroll 8
        for (int k = 0; k < 32; k++) {
            float av[8], bv[8];
            load8(av, &s_a[k * TM + R0]);
            load8(bv, &s_w[k * H  + C0]);
#pragma unroll
            for (int i = 0; i < 8; i++)
#pragma unroll
                for (int j = 0; j < 8; j++)
                    acc[i][j] = fmaf(av[i], bv[j], acc[i][j]);
        }
        __syncthreads();
    }
#pragma unroll
    for (int i = 0; i < 8; i++)
#pragma unroll
        for (int j = 0; j < 8; j++) acc[i][j] += s_tb[C0 + j];

    // LN stats, store scaled to sX cols 0..255
#pragma unroll
    for (int i = 0; i < 8; i++) {
        float s = 0.f, q = 0.f;
#pragma unroll
        for (int j = 0; j < 8; j++) { float v = acc[i][j]; s += v; q = fmaf(v, v, q); }
#pragma unroll
        for (int off = 16; off; off >>= 1) {
            s += __shfl_xor_sync(0xffffffffu, s, off);
            q += __shfl_xor_sync(0xffffffffu, q, off);
        }
        float m   = s * (1.f / H);
        float inv = rsqrtf(fmaf(q, 1.f / H, -m * m) + EPSLN);
        if (cg == 0) s_at[R0 + i] = -inv * m;
        float4 v0 = make_float4(acc[i][0]*inv, acc[i][1]*inv, acc[i][2]*inv, acc[i][3]*inv);
        float4 v1 = make_float4(acc[i][4]*inv, acc[i][5]*inv, acc[i][6]*inv, acc[i][7]*inv);
        *(float4*)&sX[(R0 + i) * 512 + C0]     = v0;
        *(float4*)&sX[(R0 + i) * 512 + C0 + 4] = v1;
    }
    __syncthreads();

    // ---- phase 3: Y[64][256] = sX(0:256) @ Ag^T + sX(256:512) @ Bg^T ----
#pragma unroll
    for (int i = 0; i < 8; i++)
#pragma unroll
        for (int j = 0; j < 8; j++) acc[i][j] = 0.f;

    for (int kt = 0; kt < 16; kt++) {
        const int kc = kt * 32;
        // stage weight tile: s_w[kk][i] = W[i][kc+kk] (W = Ag for kc<256 else Bg)
        {
            const float* base = (kc < 256) ? (g_Ag + tid * H + kc)
                                           : (g_Bg + tid * H + (kc - 256));
            const float4* src = (const float4*)base;
#pragma unroll
            for (int u = 0; u < 8; u++) {
                float4 v = src[u];
                s_w[(u * 4 + 0) * H + tid] = v.x;
                s_w[(u * 4 + 1) * H + tid] = v.y;
                s_w[(u * 4 + 2) * H + tid] = v.z;
                s_w[(u * 4 + 3) * H + tid] = v.w;
            }
        }
        __syncthreads();
#pragma unroll 8
        for (int k = 0; k < 32; k++) {
            const int c = kc + k;
            float bv[8];
            load8(bv, &s_w[k * H + C0]);
            float av[8];
#pragma unroll
            for (int i = 0; i < 8; i++) av[i] = sX[(R0 + i) * 512 + c];  // warp-broadcast
#pragma unroll
            for (int i = 0; i < 8; i++)
#pragma unroll
                for (int j = 0; j < 8; j++)
                    acc[i][j] = fmaf(av[i], bv[j], acc[i][j]);
        }
        __syncthreads();
    }

    // rank-1 LN-mean corrections + fused constant
    {
        float uA[8], uB[8], ee[8];
        load8(uA, &s_uA[C0]);
        load8(uB, &s_uB[C0]);
        load8(ee, &s_e [C0]);
#pragma unroll
        for (int i = 0; i < 8; i++) {
            float at = s_at[R0 + i];
            float ab = s_ab[R0 + i];
#pragma unroll
            for (int j = 0; j < 8; j++)
                acc[i][j] = fmaf(at, uA[j], fmaf(ab, uB[j], acc[i][j] + ee[j]));
        }
    }

    // ---- phase 4: final LN + ReLU + 2-way head ----
    float cgv[8], cbv[8], w0v[8], w1v[8];
    load8(cgv, &s_cg[C0]);
    load8(cbv, &s_cb[C0]);
    load8(w0v, &s_c2[C0]);
    load8(w1v, &s_c2[H + C0]);

#pragma unroll
    for (int i = 0; i < 8; i++) {
        float s = 0.f, q = 0.f;
#pragma unroll
        for (int j = 0; j < 8; j++) { float v = acc[i][j]; s += v; q = fmaf(v, v, q); }
#pragma unroll
        for (int off = 16; off; off >>= 1) {
            s += __shfl_xor_sync(0xffffffffu, s, off);
            q += __shfl_xor_sync(0xffffffffu, q, off);
        }
        float m   = s * (1.f / H);
        float inv = rsqrtf(fmaf(q, 1.f / H, -m * m) + EPSLN);
        float p0 = 0.f, p1 = 0.f;
#pragma unroll
        for (int j = 0; j < 8; j++) {
            float h = fmaf((acc[i][j] - m) * inv, cgv[j], cbv[j]);
            h = fmaxf(h, 0.f);
            p0 = fmaf(h, w0v[j], p0);
            p1 = fmaf(h, w1v[j], p1);
        }
#pragma unroll
        for (int off = 16; off; off >>= 1) {
            p0 += __shfl_xor_sync(0xffffffffu, p0, off);
            p1 += __shfl_xor_sync(0xffffffffu, p1, off);
        }
        if (cg == 0) {
            int r = row0 + R0 + i;
            out[2 * r + 0] = p0 + c2b0;
            out[2 * r + 1] = p1 + c2b1;
        }
    }
}

// ---------------- launch ----------------
extern "C" void kernel_launch(void* const* d_in, const int* in_sizes, int n_in,
                              void* d_out, int out_size) {
    const float* bio       = (const float*)d_in[0];
    const float* text      = (const float*)d_in[1];
    const float* bio_w     = (const float*)d_in[2];
    const float* bio_b     = (const float*)d_in[3];
    const float* text_w    = (const float*)d_in[4];
    const float* text_b    = (const float*)d_in[5];
    const float* ln_bio_g  = (const float*)d_in[6];
    const float* ln_bio_b  = (const float*)d_in[7];
    const float* ln_text_g = (const float*)d_in[8];
    const float* ln_text_b = (const float*)d_in[9];
    const float* in_proj_w = (const float*)d_in[10];
    const float* in_proj_b = (const float*)d_in[11];
    const float* out_w     = (const float*)d_in[12];
    const float* out_b     = (const float*)d_in[13];
    const float* cls1_w    = (const float*)d_in[14];
    const float* cls1_b    = (const float*)d_in[15];
    const float* cls_ln_g  = (const float*)d_in[16];
    const float* cls_ln_b  = (const float*)d_in[17];
    const float* cls2_w    = (const float*)d_in[18];
    const float* cls2_b    = (const float*)d_in[19];
    float* out = (float*)d_out;

    const int B = in_sizes[0] / BIO;   // 65536

    precompute1<<<H, NTHR>>>(in_proj_w, in_proj_b, out_w, out_b);
    precompute2<<<H, NTHR>>>(cls1_w, cls1_b, ln_text_g, ln_text_b, ln_bio_g, ln_bio_b);

    cudaFuncSetAttribute(fused_main, cudaFuncAttributeMaxDynamicSharedMemorySize, SMEM_BYTES);
    fused_main<<<B / TM, NTHR, SMEM_BYTES>>>(bio, text, bio_w, bio_b,
                                             text_w, text_b,
                                             cls_ln_g, cls_ln_b,
                                             cls2_w, cls2_b, out);
}

// round 7
// speedup vs baseline: 1.0507x; 1.0507x over previous
#include <cuda_runtime.h>

// ---------------- constants ----------------
#define H      256      // hidden
#define TXT    768
#define BIO    32
#define TM     64       // rows per CTA
#define NTHR   256
#define EPSLN  1e-5f
#define PR     8        // rows per CTA in precompute kernels

typedef unsigned long long u64;

// ---------------- device scratch (precomputed folded weights) ----------------
__device__ float g_M [H * H];   // out_w @ Wv
__device__ float g_c [H];       // out_w @ bv + out_b
__device__ float g_Ag[H * H];   // (W1L @ M) * ln_text_g (column scaled)
__device__ float g_Bg[H * H];   // (W1R @ M) * ln_bio_g
__device__ float g_uA[H];       // (W1L@M) @ ln_text_g
__device__ float g_uB[H];       // (W1R@M) @ ln_bio_g
__device__ float g_e [H];       // (W1L@M)@ln_text_b + (W1R@M)@ln_bio_b + (W1L+W1R)@c + cls1_b

// ---------------- packed f32x2 helpers ----------------
__device__ __forceinline__ u64 pack_dup(float x) {
    u64 r; unsigned xi = __float_as_uint(x);
    asm("mov.b64 %0, {%1, %1};" : "=l"(r) : "r"(xi));
    return r;
}
__device__ __forceinline__ void ffma2(u64& d, u64 a, u64 b) {
    asm("fma.rn.f32x2 %0, %1, %2, %0;" : "+l"(d) : "l"(a), "l"(b));
}
__device__ __forceinline__ void unpack2(u64 v, float& lo, float& hi) {
    unsigned a, b;
    asm("mov.b64 {%0, %1}, %2;" : "=r"(a), "=r"(b) : "l"(v));
    lo = __uint_as_float(a); hi = __uint_as_float(b);
}

// ---------------- precompute 1: M = out_w @ Wv ; c = out_w @ bv + out_b ----------------
// 8 rows per CTA -> Wv streamed once per 8 output rows (8MB L2 total)
__global__ void precompute1(const float* __restrict__ in_proj_w,
                            const float* __restrict__ in_proj_b,
                            const float* __restrict__ out_w,
                            const float* __restrict__ out_b) {
    __shared__ float s_row[PR][H];
    __shared__ float s_part[8][PR];
    const int i0 = blockIdx.x * PR;
    const int j  = threadIdx.x;
    const int lane = j & 31, wrp = j >> 5;

#pragma unroll
    for (int r = 0; r < PR; r++) s_row[r][j] = out_w[(i0 + r) * H + j];
    __syncthreads();

    float acc[PR];
#pragma unroll
    for (int r = 0; r < PR; r++) acc[r] = 0.f;
#pragma unroll 4
    for (int k = 0; k < H; k++) {
        float w = in_proj_w[(2 * H + k) * H + j];
#pragma unroll
        for (int r = 0; r < PR; r++) acc[r] = fmaf(s_row[r][k], w, acc[r]);
    }
#pragma unroll
    for (int r = 0; r < PR; r++) g_M[(i0 + r) * H + j] = acc[r];

    // c[i] = dot(out_w[i], bv) + out_b[i]
    float bv = in_proj_b[2 * H + j];
    float cv[PR];
#pragma unroll
    for (int r = 0; r < PR; r++) {
        float v = s_row[r][j] * bv;
#pragma unroll
        for (int off = 16; off; off >>= 1) v += __shfl_xor_sync(0xffffffffu, v, off);
        cv[r] = v;
    }
    if (lane == 0)
#pragma unroll
        for (int r = 0; r < PR; r++) s_part[wrp][r] = cv[r];
    __syncthreads();
    if (j < PR) {
        float s = 0.f;
#pragma unroll
        for (int w = 0; w < 8; w++) s += s_part[w][j];
        g_c[i0 + j] = s + out_b[i0 + j];
    }
}

// ---------------- precompute 2: Ag, Bg, uA, uB, e (8 rows per CTA) ----------------
__global__ void precompute2(const float* __restrict__ cls1_w,
                            const float* __restrict__ cls1_b,
                            const float* __restrict__ ln_text_g,
                            const float* __restrict__ ln_text_b,
                            const float* __restrict__ ln_bio_g,
                            const float* __restrict__ ln_bio_b) {
    __shared__ float s_l[PR][H], s_r[PR][H];
    __shared__ float s_part[8][3 * PR];
    const int i0 = blockIdx.x * PR;
    const int j  = threadIdx.x;
    const int lane = j & 31, wrp = j >> 5;

#pragma unroll
    for (int r = 0; r < PR; r++) {
        s_l[r][j] = cls1_w[(i0 + r) * 2 * H + j];
        s_r[r][j] = cls1_w[(i0 + r) * 2 * H + H + j];
    }
    __syncthreads();

    float a[PR], b[PR];
#pragma unroll
    for (int r = 0; r < PR; r++) { a[r] = 0.f; b[r] = 0.f; }
#pragma unroll 4
    for (int k = 0; k < H; k++) {
        float m = g_M[k * H + j];
#pragma unroll
        for (int r = 0; r < PR; r++) {
            a[r] = fmaf(s_l[r][k], m, a[r]);
            b[r] = fmaf(s_r[r][k], m, b[r]);
        }
    }
    float gt = ln_text_g[j], gb = ln_bio_g[j];
    float lt = ln_text_b[j], lb = ln_bio_b[j];
    float cc = g_c[j];

    float vals[3 * PR];
#pragma unroll
    for (int r = 0; r < PR; r++) {
        float ag = a[r] * gt, bg = b[r] * gb;
        g_Ag[(i0 + r) * H + j] = ag;
        g_Bg[(i0 + r) * H + j] = bg;
        vals[r]          = ag;
        vals[PR + r]     = bg;
        vals[2 * PR + r] = a[r] * lt + b[r] * lb + (s_l[r][j] + s_r[r][j]) * cc;
    }
#pragma unroll
    for (int q = 0; q < 3 * PR; q++) {
        float v = vals[q];
#pragma unroll
        for (int off = 16; off; off >>= 1) v += __shfl_xor_sync(0xffffffffu, v, off);
        vals[q] = v;
    }
    if (lane == 0)
#pragma unroll
        for (int q = 0; q < 3 * PR; q++) s_part[wrp][q] = vals[q];
    __syncthreads();
    if (j < 3 * PR) {
        float s = 0.f;
#pragma unroll
        for (int w = 0; w < 8; w++) s += s_part[w][j];
        int q = j / PR, r = j % PR;
        if (q == 0) g_uA[i0 + r] = s;
        else if (q == 1) g_uB[i0 + r] = s;
        else g_e[i0 + r] = s + cls1_b[i0 + r];
    }
}

// ---------------- main fused kernel ----------------
__device__ __forceinline__ void load8(float* d, const float* p) {
    float4 v0 = *(const float4*)p;
    float4 v1 = *(const float4*)(p + 4);
    d[0] = v0.x; d[1] = v0.y; d[2] = v0.z; d[3] = v0.w;
    d[4] = v1.x; d[5] = v1.y; d[6] = v1.z; d[7] = v1.w;
}
__device__ __forceinline__ void loadB4(u64* b, const float* p) {
    ulonglong2 q0 = *(const ulonglong2*)p;
    ulonglong2 q1 = *(const ulonglong2*)(p + 4);
    b[0] = q0.x; b[1] = q0.y; b[2] = q1.x; b[3] = q1.y;
}

// smem floats: sX 32768 | s_w 8192 | s_a 2048 | vectors 2432  => 45440 floats
#define SMEM_FLOATS 45440
#define SMEM_BYTES  (SMEM_FLOATS * 4)

__global__ __launch_bounds__(NTHR, 1)
void fused_main(const float* __restrict__ bio,
                const float* __restrict__ text,
                const float* __restrict__ bio_w,
                const float* __restrict__ bio_b,
                const float* __restrict__ text_w,
                const float* __restrict__ text_b,
                const float* __restrict__ cls_ln_g,
                const float* __restrict__ cls_ln_b,
                const float* __restrict__ cls2_w,
                const float* __restrict__ cls2_b,
                float* __restrict__ out) {
    extern __shared__ float sm[];
    float* sX   = sm;                  // [64][512] : cols 0..255 = scaled x_t, 256..511 = scaled x_b
    float* s_w  = sX  + TM * 512;      // [32][256] staging (weights)
    float* s_a  = s_w + 32 * H;        // [32][64]  staging (activations, k-major)
    float* s_uA = s_a + 32 * TM;       // 256
    float* s_uB = s_uA + H;            // 256
    float* s_e  = s_uB + H;            // 256
    float* s_cg = s_e  + H;            // 256 cls_ln_g
    float* s_cb = s_cg + H;            // 256 cls_ln_b
    float* s_c2 = s_cb + H;            // 512 cls2_w
    float* s_tb = s_c2 + 2 * H;        // 256 text_b
    float* s_bb = s_tb + H;            // 256 bio_b
    float* s_at = s_bb + H;            // 64 alpha_text = -inv_t * m_t
    float* s_ab = s_at + TM;           // 64 alpha_bio

    const int tid = threadIdx.x;
    const int rg  = tid >> 5;          // warp id = row group (0..7)
    const int cg  = tid & 31;          // lane    = col group (0..31)
    const int R0  = rg * 8;
    const int C0  = cg * 8;
    const int row0 = blockIdx.x * TM;

    const float c2b0 = cls2_b[0];
    const float c2b1 = cls2_b[1];

    // ---- phase 0: stage small vectors + bio operands ----
    s_uA[tid] = g_uA[tid];
    s_uB[tid] = g_uB[tid];
    s_e [tid] = g_e [tid];
    s_cg[tid] = cls_ln_g[tid];
    s_cb[tid] = cls_ln_b[tid];
    s_c2[tid]       = cls2_w[tid];
    s_c2[H + tid]   = cls2_w[H + tid];
    s_tb[tid] = text_b[tid];
    s_bb[tid] = bio_b[tid];
    // bio_w [256][32] -> s_w[k][c]
    for (int idx = tid; idx < BIO * H; idx += NTHR) {
        int c = idx >> 5, k = idx & 31;
        s_w[k * H + c] = bio_w[idx];
    }
    // bio tile [64][32] -> s_a[k][r]
    for (int idx = tid; idx < TM * BIO; idx += NTHR) {
        int r = idx >> 5, k = idx & 31;
        s_a[k * TM + r] = bio[(row0 + r) * BIO + k];
    }
    __syncthreads();

    u64   acc2[8][4];
    float acc [8][8];

    // ---- phase 1: bio GEMM  X_b[64][256] = bio @ bio_w^T + bio_b ----
#pragma unroll
    for (int i = 0; i < 8; i++)
#pragma unroll
        for (int j = 0; j < 4; j++) acc2[i][j] = 0ull;

#pragma unroll 8
    for (int k = 0; k < BIO; k++) {
        float av[8]; u64 bv[4];
        load8(av, &s_a[k * TM + R0]);
        loadB4(bv, &s_w[k * H + C0]);
#pragma unroll
        for (int i = 0; i < 8; i++) {
            u64 aa = pack_dup(av[i]);
#pragma unroll
            for (int j = 0; j < 4; j++) ffma2(acc2[i][j], aa, bv[j]);
        }
    }
#pragma unroll
    for (int i = 0; i < 8; i++)
#pragma unroll
        for (int j = 0; j < 4; j++) {
            unpack2(acc2[i][j], acc[i][2 * j], acc[i][2 * j + 1]);
            acc[i][2 * j]     += s_bb[C0 + 2 * j];
            acc[i][2 * j + 1] += s_bb[C0 + 2 * j + 1];
        }

    // LN stats per row (warp owns rows R0..R0+7), store scaled to sX cols 256..511
#pragma unroll
    for (int i = 0; i < 8; i++) {
        float s = 0.f, q = 0.f;
#pragma unroll
        for (int j = 0; j < 8; j++) { float v = acc[i][j]; s += v; q = fmaf(v, v, q); }
#pragma unroll
        for (int off = 16; off; off >>= 1) {
            s += __shfl_xor_sync(0xffffffffu, s, off);
            q += __shfl_xor_sync(0xffffffffu, q, off);
        }
        float m   = s * (1.f / H);
        float inv = rsqrtf(fmaf(q, 1.f / H, -m * m) + EPSLN);
        if (cg == 0) s_ab[R0 + i] = -inv * m;
        float4 v0 = make_float4(acc[i][0]*inv, acc[i][1]*inv, acc[i][2]*inv, acc[i][3]*inv);
        float4 v1 = make_float4(acc[i][4]*inv, acc[i][5]*inv, acc[i][6]*inv, acc[i][7]*inv);
        *(float4*)&sX[(R0 + i) * 512 + 256 + C0]     = v0;
        *(float4*)&sX[(R0 + i) * 512 + 256 + C0 + 4] = v1;
    }
    __syncthreads();

    // ---- phase 2: text GEMM  X_t[64][256] = text @ text_w^T + text_b ----
#pragma unroll
    for (int i = 0; i < 8; i++)
#pragma unroll
        for (int j = 0; j < 4; j++) acc2[i][j] = 0ull;

    for (int kt = 0; kt < TXT / 32; kt++) {
        const int k0 = kt * 32;
        // stage text tile -> s_a[k][r]  (2048 floats, 512 float4)
#pragma unroll
        for (int u = 0; u < 2; u++) {
            int qd = tid + u * NTHR;           // 0..511
            int r  = qd >> 3;                  // 0..63
            int kq = qd & 7;                   // float4 index within 32 k
            float4 v = *(const float4*)&text[(row0 + r) * TXT + k0 + kq * 4];
            s_a[(kq * 4 + 0) * TM + r] = v.x;
            s_a[(kq * 4 + 1) * TM + r] = v.y;
            s_a[(kq * 4 + 2) * TM + r] = v.z;
            s_a[(kq * 4 + 3) * TM + r] = v.w;
        }
        // stage text_w tile -> s_w[k][c] (thread = output channel, 32B contiguous read)
        {
            const float4* src = (const float4*)&text_w[tid * TXT + k0];
#pragma unroll
            for (int u = 0; u < 8; u++) {
                float4 v = src[u];
                s_w[(u * 4 + 0) * H + tid] = v.x;
                s_w[(u * 4 + 1) * H + tid] = v.y;
                s_w[(u * 4 + 2) * H + tid] = v.z;
                s_w[(u * 4 + 3) * H + tid] = v.w;
            }
        }
        __syncthreads();
#pragma unroll 8
        for (int k = 0; k < 32; k++) {
            float av[8]; u64 bv[4];
            load8(av, &s_a[k * TM + R0]);
            loadB4(bv, &s_w[k * H + C0]);
#pragma unroll
            for (int i = 0; i < 8; i++) {
                u64 aa = pack_dup(av[i]);
#pragma unroll
                for (int j = 0; j < 4; j++) ffma2(acc2[i][j], aa, bv[j]);
            }
        }
        __syncthreads();
    }
#pragma unroll
    for (int i = 0; i < 8; i++)
#pragma unroll
        for (int j = 0; j < 4; j++) {
            unpack2(acc2[i][j], acc[i][2 * j], acc[i][2 * j + 1]);
            acc[i][2 * j]     += s_tb[C0 + 2 * j];
            acc[i][2 * j + 1] += s_tb[C0 + 2 * j + 1];
        }

    // LN stats, store scaled to sX cols 0..255
#pragma unroll
    for (int i = 0; i < 8; i++) {
        float s = 0.f, q = 0.f;
#pragma unroll
        for (int j = 0; j < 8; j++) { float v = acc[i][j]; s += v; q = fmaf(v, v, q); }
#pragma unroll
        for (int off = 16; off; off >>= 1) {
            s += __shfl_xor_sync(0xffffffffu, s, off);
            q += __shfl_xor_sync(0xffffffffu, q, off);
        }
        float m   = s * (1.f / H);
        float inv = rsqrtf(fmaf(q, 1.f / H, -m * m) + EPSLN);
        if (cg == 0) s_at[R0 + i] = -inv * m;
        float4 v0 = make_float4(acc[i][0]*inv, acc[i][1]*inv, acc[i][2]*inv, acc[i][3]*inv);
        float4 v1 = make_float4(acc[i][4]*inv, acc[i][5]*inv, acc[i][6]*inv, acc[i][7]*inv);
        *(float4*)&sX[(R0 + i) * 512 + C0]     = v0;
        *(float4*)&sX[(R0 + i) * 512 + C0 + 4] = v1;
    }
    __syncthreads();

    // ---- phase 3: Y[64][256] = sX(0:256) @ Ag^T + sX(256:512) @ Bg^T ----
#pragma unroll
    for (int i = 0; i < 8; i++)
#pragma unroll
        for (int j = 0; j < 4; j++) acc2[i][j] = 0ull;

    for (int kt = 0; kt < 16; kt++) {
        const int kc = kt * 32;
        // stage weight tile: s_w[kk][i] = W[i][kc+kk] (W = Ag for kc<256 else Bg)
        {
            const float* base = (kc < 256) ? (g_Ag + tid * H + kc)
                                           : (g_Bg + tid * H + (kc - 256));
            const float4* src = (const float4*)base;
#pragma unroll
            for (int u = 0; u < 8; u++) {
                float4 v = src[u];
                s_w[(u * 4 + 0) * H + tid] = v.x;
                s_w[(u * 4 + 1) * H + tid] = v.y;
                s_w[(u * 4 + 2) * H + tid] = v.z;
                s_w[(u * 4 + 3) * H + tid] = v.w;
            }
        }
        __syncthreads();
#pragma unroll 8
        for (int k = 0; k < 32; k++) {
            const int c = kc + k;
            u64 bv[4];
            loadB4(bv, &s_w[k * H + C0]);
#pragma unroll
            for (int i = 0; i < 8; i++) {
                u64 aa = pack_dup(sX[(R0 + i) * 512 + c]);   // warp-broadcast LDS
#pragma unroll
                for (int j = 0; j < 4; j++) ffma2(acc2[i][j], aa, bv[j]);
            }
        }
        __syncthreads();
    }
#pragma unroll
    for (int i = 0; i < 8; i++)
#pragma unroll
        for (int j = 0; j < 4; j++)
            unpack2(acc2[i][j], acc[i][2 * j], acc[i][2 * j + 1]);

    // rank-1 LN-mean corrections + fused constant
    {
        float uA[8], uB[8], ee[8];
        load8(uA, &s_uA[C0]);
        load8(uB, &s_uB[C0]);
        load8(ee, &s_e [C0]);
#pragma unroll
        for (int i = 0; i < 8; i++) {
            float at = s_at[R0 + i];
            float ab = s_ab[R0 + i];
#pragma unroll
            for (int j = 0; j < 8; j++)
                acc[i][j] = fmaf(at, uA[j], fmaf(ab, uB[j], acc[i][j] + ee[j]));
        }
    }

    // ---- phase 4: final LN + ReLU + 2-way head ----
    float cgv[8], cbv[8], w0v[8], w1v[8];
    load8(cgv, &s_cg[C0]);
    load8(cbv, &s_cb[C0]);
    load8(w0v, &s_c2[C0]);
    load8(w1v, &s_c2[H + C0]);

#pragma unroll
    for (int i = 0; i < 8; i++) {
        float s = 0.f, q = 0.f;
#pragma unroll
        for (int j = 0; j < 8; j++) { float v = acc[i][j]; s += v; q = fmaf(v, v, q); }
#pragma unroll
        for (int off = 16; off; off >>= 1) {
            s += __shfl_xor_sync(0xffffffffu, s, off);
            q += __shfl_xor_sync(0xffffffffu, q, off);
        }
        float m   = s * (1.f / H);
        float inv = rsqrtf(fmaf(q, 1.f / H, -m * m) + EPSLN);
        float p0 = 0.f, p1 = 0.f;
#pragma unroll
        for (int j = 0; j < 8; j++) {
            float h = fmaf((acc[i][j] - m) * inv, cgv[j], cbv[j]);
            h = fmaxf(h, 0.f);
            p0 = fmaf(h, w0v[j], p0);
            p1 = fmaf(h, w1v[j], p1);
        }
#pragma unroll
        for (int off = 16; off; off >>= 1) {
            p0 += __shfl_xor_sync(0xffffffffu, p0, off);
            p1 += __shfl_xor_sync(0xffffffffu, p1, off);
        }
        if (cg == 0) {
            int r = row0 + R0 + i;
            out[2 * r + 0] = p0 + c2b0;
            out[2 * r + 1] = p1 + c2b1;
        }
    }
}

// ---------------- launch ----------------
extern "C" void kernel_launch(void* const* d_in, const int* in_sizes, int n_in,
                              void* d_out, int out_size) {
    const float* bio       = (const float*)d_in[0];
    const float* text      = (const float*)d_in[1];
    const float* bio_w     = (const float*)d_in[2];
    const float* bio_b     = (const float*)d_in[3];
    const float* text_w    = (const float*)d_in[4];
    const float* text_b    = (const float*)d_in[5];
    const float* ln_bio_g  = (const float*)d_in[6];
    const float* ln_bio_b  = (const float*)d_in[7];
    const float* ln_text_g = (const float*)d_in[8];
    const float* ln_text_b = (const float*)d_in[9];
    const float* in_proj_w = (const float*)d_in[10];
    const float* in_proj_b = (const float*)d_in[11];
    const float* out_w     = (const float*)d_in[12];
    const float* out_b     = (const float*)d_in[13];
    const float* cls1_w    = (const float*)d_in[14];
    const float* cls1_b    = (const float*)d_in[15];
    const float* cls_ln_g  = (const float*)d_in[16];
    const float* cls_ln_b  = (const float*)d_in[17];
    const float* cls2_w    = (const float*)d_in[18];
    const float* cls2_b    = (const float*)d_in[19];
    float* out = (float*)d_out;

    const int B = in_sizes[0] / BIO;   // 65536

    precompute1<<<H / PR, NTHR>>>(in_proj_w, in_proj_b, out_w, out_b);
    precompute2<<<H / PR, NTHR>>>(cls1_w, cls1_b, ln_text_g, ln_text_b, ln_bio_g, ln_bio_b);

    cudaFuncSetAttribute(fused_main, cudaFuncAttributeMaxDynamicSharedMemorySize, SMEM_BYTES);
    fused_main<<<B / TM, NTHR, SMEM_BYTES>>>(bio, text, bio_w, bio_b,
                                             text_w, text_b,
                                             cls_ln_g, cls_ln_b,
                                             cls2_w, cls2_b, out);
}